// round 3
// baseline (speedup 1.0000x reference)
#include <cuda_runtime.h>
#include <cuda_bf16.h>

#define T_LEN 1024
#define C_DIM 8
#define B_SZ  64
#define ALPHA_ 0.7f
#define GAMMA_ 0.2f
#define INF_   1000000000.0f

// exp/log base-2 constants: exp((mn-x)/g) = exp2((mn-x)*KEXP), g*ln(s) = KLOG*log2(s)
#define KEXP_ 7.2134752f    // (1/GAMMA) * log2(e)
#define KLOG_ 0.13862944f   // GAMMA * ln(2)

__device__ float g_mse_b[B_SZ];
__device__ float g_sdtw[B_SZ];

// ---------------------------------------------------------------------------
// Soft-DTW + fused per-batch MSE partial: one CTA per batch, anti-diagonal
// wavefront, thread i owns row i.
//   tg rows padded to 36 floats -> conflict-free LDS.128 on diagonals.
//   3 rotating R buffers with INF sentinel at slot 0 -> one barrier per step.
//   left value carried in a register; distance d software-pipelined so the
//   post-barrier chain is LDS(up,diag) -> min -> 2xEX2 -> LG2 -> store.
// ---------------------------------------------------------------------------
__global__ __launch_bounds__(1024, 1)
void sdtw_kernel(const float* __restrict__ pred,
                 const float* __restrict__ target) {
    extern __shared__ float sm[];
    float* tg   = sm;                        // T_LEN * 36
    float* y2   = tg + T_LEN * 36;           // T_LEN
    float* rb   = y2 + T_LEN;                // 3 * (T_LEN + 1)
    float* wred = rb + 3 * (T_LEN + 1);      // 32 (mse warp sums)

    const int i = threadIdx.x;
    const int b = blockIdx.x;

    const float4* pg = (const float4*)(pred + (size_t)b * T_LEN * C_DIM);
    const float4* gg = (const float4*)(target + (size_t)b * T_LEN * C_DIM);

    float4 p0 = pg[2 * i];
    float4 p1 = pg[2 * i + 1];
    float4 t0 = gg[2 * i];
    float4 t1 = gg[2 * i + 1];

    ((float4*)(tg + i * 36))[0] = t0;
    ((float4*)(tg + i * 36 + 4))[0] = t1;
    y2[i] = t0.x * t0.x + t0.y * t0.y + t0.z * t0.z + t0.w * t0.w +
            t1.x * t1.x + t1.y * t1.y + t1.z * t1.z + t1.w * t1.w;
    const float x2 = p0.x * p0.x + p0.y * p0.y + p0.z * p0.z + p0.w * p0.w +
                     p1.x * p1.x + p1.y * p1.y + p1.z * p1.z + p1.w * p1.w;

    // fused MSE partial for this batch (pred/target rows already in regs)
    {
        float dx, acc = 0.f;
        dx = p0.x - t0.x; acc = fmaf(dx, dx, acc);
        dx = p0.y - t0.y; acc = fmaf(dx, dx, acc);
        dx = p0.z - t0.z; acc = fmaf(dx, dx, acc);
        dx = p0.w - t0.w; acc = fmaf(dx, dx, acc);
        dx = p1.x - t1.x; acc = fmaf(dx, dx, acc);
        dx = p1.y - t1.y; acc = fmaf(dx, dx, acc);
        dx = p1.z - t1.z; acc = fmaf(dx, dx, acc);
        dx = p1.w - t1.w; acc = fmaf(dx, dx, acc);
#pragma unroll
        for (int o = 16; o; o >>= 1) acc += __shfl_xor_sync(0xffffffffu, acc, o);
        if ((i & 31) == 0) wred[i >> 5] = acc;
    }

    // init all three R buffers (incl. sentinels at slot 0) to INF
    for (int idx = i; idx < 3 * (T_LEN + 1); idx += 1024) rb[idx] = INF_;
    __syncthreads();

    if (i == 0) {
        float m = 0.f;
#pragma unroll
        for (int w = 0; w < 32; ++w) m += wred[w];
        g_mse_b[b] = m;
    }

    float* km2 = rb;                       // r_{k-2}, slot s holds index s-1
    float* km1 = rb + (T_LEN + 1);         // r_{k-1}
    float* W   = rb + 2 * (T_LEN + 1);     // r_k being written

    float prev = INF_;   // r_{k-1}[i] carried in register ("left")
    float last = INF_;

    // d for step k=0 (only thread 0 uses it; j clamps to 0)
    float d_cur;
    {
        const float4* tr = (const float4*)(tg);
        float4 a = tr[0], c = tr[1];
        float dot = fmaf(p0.x, a.x, fmaf(p0.y, a.y, fmaf(p0.z, a.z,
                    fmaf(p0.w, a.w, fmaf(p1.x, c.x, fmaf(p1.y, c.y,
                    fmaf(p1.z, c.z, p1.w * c.w)))))));
        d_cur = fmaf(-2.f, dot, x2 + y2[0]);
    }

    for (int k = 0; k < 2 * T_LEN - 1; ++k) {
        const int j = k - i;
        float val = INF_;
        if ((unsigned)j < (unsigned)T_LEN) {
            float up = km1[i];           // r_{k-1}[i-1]
            float dg = km2[i];           // r_{k-2}[i-1]
            if (k == 0) dg = 0.f;        // only i==0 reaches here at k==0
            float lf = prev;             // r_{k-1}[i] from register

            float mn = fminf(up, fminf(lf, dg));
            float mx = fmaxf(up, fmaxf(lf, dg));
            // diffs (mn-up, mn-lf, mn-dg): one is 0; exponentiate the other two
            float dsum = fmaf(3.f, mn, -(up + lf + dg));
            float dm   = mn - mx;        // most negative diff
            float dmid = dsum - dm;      // middle diff
            float s = 1.f + exp2f(dm * KEXP_) + exp2f(dmid * KEXP_);
            val = d_cur + mn - KLOG_ * __log2f(s);
        }
        W[i + 1] = val;
        prev = val;
        last = val;

        // software-pipelined distance for step k+1 (overlaps barrier wait)
        const int jn = k + 1 - i;
        if ((unsigned)jn < (unsigned)T_LEN) {
            const float4* tr = (const float4*)(tg + jn * 36);
            float4 a = tr[0], c = tr[1];
            float dot = fmaf(p0.x, a.x, fmaf(p0.y, a.y, fmaf(p0.z, a.z,
                        fmaf(p0.w, a.w, fmaf(p1.x, c.x, fmaf(p1.y, c.y,
                        fmaf(p1.z, c.z, p1.w * c.w)))))));
            d_cur = fmaf(-2.f, dot, x2 + y2[jn]);
        }

        __syncthreads();
        float* tmp = km2; km2 = km1; km1 = W; W = tmp;
    }

    if (i == T_LEN - 1) g_sdtw[b] = last;   // R[T-1][T-1]
}

// ---------------------------------------------------------------------------
// Final deterministic reduction -> out[0]
// ---------------------------------------------------------------------------
__global__ void final_kernel(float* __restrict__ out) {
    const int t = threadIdx.x;  // 64
    float m  = g_mse_b[t];
    float sd = g_sdtw[t];
#pragma unroll
    for (int o = 16; o; o >>= 1) {
        m  += __shfl_xor_sync(0xffffffffu, m, o);
        sd += __shfl_xor_sync(0xffffffffu, sd, o);
    }
    __shared__ float sm_[2], ss_[2];
    if ((t & 31) == 0) { sm_[t >> 5] = m; ss_[t >> 5] = sd; }
    __syncthreads();
    if (t == 0) {
        float M = sm_[0] + sm_[1];
        float S = ss_[0] + ss_[1];
        float mse  = M / (float)(B_SZ * T_LEN * C_DIM);
        float sdtw = S / (float)B_SZ;
        out[0] = ALPHA_ * mse + (1.0f - ALPHA_) * sdtw;
    }
}

// ---------------------------------------------------------------------------
extern "C" void kernel_launch(void* const* d_in, const int* in_sizes, int n_in,
                              void* d_out, int out_size) {
    const float* pred   = (const float*)d_in[0];
    const float* target = (const float*)d_in[1];
    float* out = (float*)d_out;

    const int smem = (T_LEN * 36 + T_LEN + 3 * (T_LEN + 1) + 32) * (int)sizeof(float);
    cudaFuncSetAttribute(sdtw_kernel,
                         cudaFuncAttributeMaxDynamicSharedMemorySize, smem);
    sdtw_kernel<<<B_SZ, 1024, smem>>>(pred, target);

    final_kernel<<<1, 64>>>(out);
}

// round 4
// speedup vs baseline: 1.0748x; 1.0748x over previous
#include <cuda_runtime.h>
#include <cuda_bf16.h>

#define T_LEN 1024
#define B_SZ  64
#define ALPHA_ 0.7f
#define GAMMA_ 0.2f
#define INF_   1000000000.0f
#define KEXP_  7.2134752f    // (1/GAMMA)*log2(e)
#define KLOG_  0.13862944f   // GAMMA*ln(2)
#define FULL_  0xffffffffu

__device__ float g_mse_b[B_SZ];
__device__ float g_sdtw[B_SZ];

__device__ __forceinline__ float ex2(float x) {
    float r; asm("ex2.approx.ftz.f32 %0, %1;" : "=f"(r) : "f"(x)); return r;
}
__device__ __forceinline__ float lg2f_(float x) {
    float r; asm("lg2.approx.ftz.f32 %0, %1;" : "=f"(r) : "f"(x)); return r;
}

// softmin of (up, lf, dg) with min-shift; one of the diffs is exactly 0.
__device__ __forceinline__ float softmin3(float up, float lf, float dg) {
    float mn   = fminf(up, fminf(lf, dg));
    float mx   = fmaxf(up, fmaxf(lf, dg));
    float dsum = fmaf(3.f, mn, -((up + lf) + dg)); // sum of 3 diffs (<=0)
    float dm   = mn - mx;                          // most negative diff
    float dmid = dsum - dm;                        // middle diff
    float s = 1.f + ex2(dm * KEXP_) + ex2(dmid * KEXP_);
    return mn - KLOG_ * lg2f_(s);
}

// ---------------------------------------------------------------------------
// Soft-DTW, warp-shuffle skewed wavefront. One CTA per batch.
// Warp w owns rows [32w, 32w+32). Chunk m of warp w = global steps
// k in [32w+32m, 32w+32m+32), executed at round r = 2w + m (m in [0,32]).
// Per step: up = shfl_up(prev), diag = previous step's up (register),
// left = prev (register). Lane 0 gets `up` from warp w-1's lane-31 value via
// a 3-phase SMEM ring written one round earlier. 95 __syncthreads total.
// ---------------------------------------------------------------------------
__global__ __launch_bounds__(1024, 1)
void sdtw_kernel(const float* __restrict__ pred,
                 const float* __restrict__ target) {
    extern __shared__ float sm[];
    float* tg   = sm;                     // T_LEN * 36 (36-float row stride)
    float* y2   = tg + T_LEN * 36;        // T_LEN
    float* bb   = y2 + T_LEN;             // 3 phases * 32 warps * 32 slots
    float* wred = bb + 3 * 32 * 32;       // 32

    const int i = threadIdx.x;
    const int w = i >> 5;
    const int l = i & 31;
    const int b = blockIdx.x;

    const float4* pg = (const float4*)(pred + (size_t)b * T_LEN * 8);
    const float4* gg = (const float4*)(target + (size_t)b * T_LEN * 8);
    float4 p0 = pg[2 * i], p1 = pg[2 * i + 1];
    float4 t0 = gg[2 * i], t1 = gg[2 * i + 1];

    ((float4*)(tg + i * 36))[0] = t0;
    ((float4*)(tg + i * 36 + 4))[0] = t1;
    y2[i] = t0.x * t0.x + t0.y * t0.y + t0.z * t0.z + t0.w * t0.w +
            t1.x * t1.x + t1.y * t1.y + t1.z * t1.z + t1.w * t1.w;
    const float x2 = p0.x * p0.x + p0.y * p0.y + p0.z * p0.z + p0.w * p0.w +
                     p1.x * p1.x + p1.y * p1.y + p1.z * p1.z + p1.w * p1.w;

    // fused per-batch MSE partial
    {
        float dx, acc = 0.f;
        dx = p0.x - t0.x; acc = fmaf(dx, dx, acc);
        dx = p0.y - t0.y; acc = fmaf(dx, dx, acc);
        dx = p0.z - t0.z; acc = fmaf(dx, dx, acc);
        dx = p0.w - t0.w; acc = fmaf(dx, dx, acc);
        dx = p1.x - t1.x; acc = fmaf(dx, dx, acc);
        dx = p1.y - t1.y; acc = fmaf(dx, dx, acc);
        dx = p1.z - t1.z; acc = fmaf(dx, dx, acc);
        dx = p1.w - t1.w; acc = fmaf(dx, dx, acc);
#pragma unroll
        for (int o = 16; o; o >>= 1) acc += __shfl_xor_sync(FULL_, acc, o);
        if (l == 0) wred[w] = acc;
    }
    __syncthreads();
    if (i == 0) {
        float msum = 0.f;
#pragma unroll
        for (int q = 0; q < 32; ++q) msum += wred[q];
        g_mse_b[b] = msum;
    }

    float prev    = INF_;
    float up_prev = (i == 0) ? 0.f : INF_;  // diag source; 0 seeds cell (0,0)
    float lastv   = INF_;

    for (int r = 0; r < 95; ++r) {
        const int m = r - 2 * w;
        if ((unsigned)m <= 32u) {
            // boundary values from warp w-1 (written rounds r-1 / r-2)
            float bv = INF_;
            if (w > 0) {
                int ph1 = (r + 2) % 3;  // (r-1) mod 3
                int ph2 = (r + 1) % 3;  // (r-2) mod 3
                bv = (l == 0) ? bb[ph2 * 1024 + (w - 1) * 32 + 31]
                              : bb[ph1 * 1024 + (w - 1) * 32 + (l - 1)];
            }
            float* wr = bb + (r % 3) * 1024 + w * 32;
            const int jbase = 32 * m - l;

            if (m >= 1 && m <= 31) {
                // interior chunk: every lane valid at every step
                const float* trow = tg + jbase * 36;
                const float* y2p  = y2 + jbase;
#pragma unroll 8
                for (int o = 0; o < 32; ++o) {
                    float bup = __shfl_sync(FULL_, bv, o);
                    float up  = __shfl_up_sync(FULL_, prev, 1);
                    if (l == 0) up = bup;
                    float dg = up_prev, lf = prev;

                    float4 a = ((const float4*)trow)[0];
                    float4 c = ((const float4*)trow)[1];
                    float dot = fmaf(p0.x, a.x, fmaf(p0.y, a.y, fmaf(p0.z, a.z,
                                fmaf(p0.w, a.w, fmaf(p1.x, c.x, fmaf(p1.y, c.y,
                                fmaf(p1.z, c.z, p1.w * c.w)))))));
                    float d = fmaf(-2.f, dot, x2 + y2p[o]);

                    float val = d + softmin3(up, lf, dg);
                    up_prev = up; prev = val; lastv = val;
                    if (l == 31) wr[o] = val;
                    trow += 36;
                }
            } else {
                // edge chunks m==0 / m==32: per-lane validity + clamped j
#pragma unroll 4
                for (int o = 0; o < 32; ++o) {
                    float bup = __shfl_sync(FULL_, bv, o);
                    float up  = __shfl_up_sync(FULL_, prev, 1);
                    if (l == 0) up = bup;
                    float dg = up_prev, lf = prev;

                    int j = jbase + o;
                    bool valid = (unsigned)j < (unsigned)T_LEN;
                    int jc = valid ? j : 0;
                    const float* trow = tg + jc * 36;
                    float4 a = ((const float4*)trow)[0];
                    float4 c = ((const float4*)trow)[1];
                    float dot = fmaf(p0.x, a.x, fmaf(p0.y, a.y, fmaf(p0.z, a.z,
                                fmaf(p0.w, a.w, fmaf(p1.x, c.x, fmaf(p1.y, c.y,
                                fmaf(p1.z, c.z, p1.w * c.w)))))));
                    float d = fmaf(-2.f, dot, x2 + y2[jc]);

                    float val = valid ? (d + softmin3(up, lf, dg)) : INF_;
                    up_prev = up; prev = val;
                    if (valid) lastv = val;
                    if (l == 31) wr[o] = val;
                }
            }
        }
        __syncthreads();
    }

    if (i == T_LEN - 1) g_sdtw[b] = lastv;   // R[T-1][T-1]
}

// ---------------------------------------------------------------------------
__global__ void final_kernel(float* __restrict__ out) {
    const int t = threadIdx.x;  // 64
    float m  = g_mse_b[t];
    float sd = g_sdtw[t];
#pragma unroll
    for (int o = 16; o; o >>= 1) {
        m  += __shfl_xor_sync(FULL_, m, o);
        sd += __shfl_xor_sync(FULL_, sd, o);
    }
    __shared__ float sm_[2], ss_[2];
    if ((t & 31) == 0) { sm_[t >> 5] = m; ss_[t >> 5] = sd; }
    __syncthreads();
    if (t == 0) {
        float M = sm_[0] + sm_[1];
        float S = ss_[0] + ss_[1];
        float mse  = M / (float)(B_SZ * T_LEN * 8);
        float sdtw = S / (float)B_SZ;
        out[0] = ALPHA_ * mse + (1.0f - ALPHA_) * sdtw;
    }
}

// ---------------------------------------------------------------------------
extern "C" void kernel_launch(void* const* d_in, const int* in_sizes, int n_in,
                              void* d_out, int out_size) {
    const float* pred   = (const float*)d_in[0];
    const float* target = (const float*)d_in[1];
    float* out = (float*)d_out;

    const int smem = (T_LEN * 36 + T_LEN + 3 * 32 * 32 + 32) * (int)sizeof(float);
    cudaFuncSetAttribute(sdtw_kernel,
                         cudaFuncAttributeMaxDynamicSharedMemorySize, smem);
    sdtw_kernel<<<B_SZ, 1024, smem>>>(pred, target);

    final_kernel<<<1, 64>>>(out);
}